// round 6
// baseline (speedup 1.0000x reference)
#include <cuda_runtime.h>
#include <math.h>
#include <cstdint>

// ---------------------------------------------------------------------------
// Problem constants: B=8192, T=15, D=H=512, MAXL=8, CENTER=7
// ---------------------------------------------------------------------------
#define B_MAX   8192
#define T_WIN   15
#define D_DIM   512
#define H_DIM   512
#define G3      1536
#define MAXL    8
#define PITCH   20

// MLP GEMM (gemm_tc): 128x128, 4 stages, 2 CTAs/SM
#define STAGES        4
#define STAGE_FLOATS  (128 * PITCH)
#define SMEM_REQ      (STAGES * STAGE_FLOATS * 4 * 2)            // 81920 B

// gather GEMM: 128x256, 4 stages, 1 CTA/SM
#define G_STAGES      4
#define GA_FLOATS     (128 * PITCH)
#define GB_FLOATS     (256 * PITCH)
#define GSMEM_REQ     (G_STAGES * (GA_FLOATS + GB_FLOATS) * 4)   // 122880 B

// fused recurrence GEMM+gate: 128 rows x 128 gate-cols x 3 gates, 3 stages
#define F_STAGES      3
#define F_TILE_FLOATS (128 * PITCH)
#define FSMEM_REQ     (F_STAGES * 4 * F_TILE_FLOATS * 4)         // 122880 B

// ---------------------------------------------------------------------------
// Scratch (__device__ globals; zero-initialized at module load)
// ---------------------------------------------------------------------------
__device__ float g_xp0[B_MAX * MAXL * G3];   // [t][sorted_i][1536] fwd
__device__ float g_xp1[B_MAX * MAXL * G3];   // bwd
__device__ float g_h0a[B_MAX * H_DIM];       // fwd h, buffer A (even steps)
__device__ float g_h0b[B_MAX * H_DIM];       // fwd h, buffer B (odd steps)
__device__ float g_h1a[B_MAX * H_DIM];       // bwd
__device__ float g_h1b[B_MAX * H_DIM];
__device__ float g_hid[B_MAX * H_DIM];
__device__ float g_winr[B_MAX * T_WIN * D_DIM];
#define WR_WIHF 0
#define WR_WHHF (G3 * D_DIM)
#define WR_WIHB (2 * G3 * D_DIM)
#define WR_WHHB (3 * G3 * D_DIM)
#define WR_W1   (4 * G3 * D_DIM)
#define WR_W2   (4 * G3 * D_DIM + H_DIM * 2 * H_DIM)
__device__ float g_wr[4 * G3 * D_DIM + H_DIM * 2 * H_DIM + H_DIM * H_DIM];

// ---- length-compaction state ----
#define MAX_CHUNKS 64
__device__ int g_chunk_hist[MAX_CHUNKS][16];
__device__ int g_chunk_base[MAX_CHUNKS][16];
__device__ int g_lrank [B_MAX];
__device__ int g_perm  [B_MAX];
__device__ int g_lenf_s[B_MAX];
__device__ int g_lenb_s[B_MAX];
__device__ int g_nt[2 * MAXL];

// ---------------------------------------------------------------------------
// PTX helpers
// ---------------------------------------------------------------------------
__device__ __forceinline__ unsigned f2tf32(float f) {
    unsigned r;
    asm("cvt.rna.tf32.f32 %0, %1;" : "=r"(r) : "f"(f));
    return r;
}

__device__ __forceinline__ void ldsm4(unsigned* r, const float* p) {
    unsigned addr = (unsigned)__cvta_generic_to_shared(p);
    asm volatile("ldmatrix.sync.aligned.m8n8.x4.shared.b16 {%0,%1,%2,%3}, [%4];"
                 : "=r"(r[0]), "=r"(r[1]), "=r"(r[2]), "=r"(r[3]) : "r"(addr));
}

__device__ __forceinline__ void mma_tf32(float* c, const unsigned* a,
                                         unsigned b0, unsigned b1) {
    asm volatile(
        "mma.sync.aligned.m16n8k8.row.col.f32.tf32.tf32.f32 "
        "{%0,%1,%2,%3}, {%4,%5,%6,%7}, {%8,%9}, {%0,%1,%2,%3};"
        : "+f"(c[0]), "+f"(c[1]), "+f"(c[2]), "+f"(c[3])
        : "r"(a[0]), "r"(a[1]), "r"(a[2]), "r"(a[3]), "r"(b0), "r"(b1));
}

__device__ __forceinline__ void cpasync16(void* sp, const void* gp) {
    unsigned sa = (unsigned)__cvta_generic_to_shared(sp);
    asm volatile("cp.async.cg.shared.global [%0], [%1], 16;"
                 :: "r"(sa), "l"(gp) : "memory");
}
#define CP_COMMIT() asm volatile("cp.async.commit_group;" ::: "memory")
#define CP_WAIT(N)  asm volatile("cp.async.wait_group %0;" :: "n"(N) : "memory")

// ---------------------------------------------------------------------------
// Pre-round fp32 -> canonical tf32
// ---------------------------------------------------------------------------
__global__ void preround(const float4* __restrict__ src,
                         float4* __restrict__ dst, int n4) {
    int i = blockIdx.x * blockDim.x + threadIdx.x;
    if (i >= n4) return;
    float4 v = src[i];
    v.x = __uint_as_float(f2tf32(v.x));
    v.y = __uint_as_float(f2tf32(v.y));
    v.z = __uint_as_float(f2tf32(v.z));
    v.w = __uint_as_float(f2tf32(v.w));
    dst[i] = v;
}

// ---------------------------------------------------------------------------
// Deterministic counting sort by window_len descending
// ---------------------------------------------------------------------------
__global__ void sort1(const int* __restrict__ wlen) {
    __shared__ int s_wl[256];
    __shared__ int s_rank[256];
    __shared__ int s_h[16];
    const int c = blockIdx.x, tid = threadIdx.x;
    s_wl[tid] = wlen[c * 256 + tid];
    if (tid < 16) s_h[tid] = 0;
    __syncthreads();
    if (tid == 0) {
        #pragma unroll 4
        for (int k = 0; k < 256; ++k) { int w = s_wl[k]; s_rank[k] = s_h[w]++; }
    }
    __syncthreads();
    g_lrank[c * 256 + tid] = s_rank[tid];
    if (tid < 16) g_chunk_hist[c][tid] = s_h[tid];
}

__global__ void sort2(int nchunks) {
    if (threadIdx.x != 0) return;
    int total[16];
    for (int w = 0; w < 16; ++w) {
        int s = 0;
        for (int c = 0; c < nchunks; ++c) s += g_chunk_hist[c][w];
        total[w] = s;
    }
    int off = 0;
    for (int w = 15; w >= 1; --w) {
        int run = off;
        for (int c = 0; c < nchunks; ++c) {
            g_chunk_base[c][w] = run;
            run += g_chunk_hist[c][w];
        }
        off += total[w];
    }
    for (int t = 0; t < MAXL; ++t) {
        int nf = 0, nb = 0;
        for (int w = 1; w <= 15; ++w) {
            if ((w - 1) / 2 + 1 > t) nf += total[w];
            if (w / 2 + 1 > t)       nb += total[w];
        }
        g_nt[t]        = nf;
        g_nt[MAXL + t] = nb;
    }
}

__global__ void sort3(const int* __restrict__ wlen) {
    const int c = blockIdx.x;
    const int i = c * 256 + threadIdx.x;
    const int w = wlen[i];
    const int pos = g_chunk_base[c][w] + g_lrank[i];
    g_perm[pos]   = i;
    g_lenf_s[pos] = (w - 1) / 2 + 1;
    g_lenb_s[pos] = w / 2 + 1;
}

// ---------------------------------------------------------------------------
// Gather GEMM: xp[t*Bn+i][1536] = window_row(t,i) @ Wih^T
// Block 128x256, 8 warps of 64x64, 4-stage cp.async, compaction early exit.
// ---------------------------------------------------------------------------
struct GathP {
    const float* win;
    const float* Bw0; const float* Bw1;
    float* C0; float* C1;
    const int* perm; const int* lenf_s; const int* lenb_s; const int* nt;
    int Bn;
};

__global__ __launch_bounds__(256, 1)
void gemm_gather256(GathP p)
{
    const int dir = blockIdx.z, bm = blockIdx.y, bn = blockIdx.x;
    const int t  = (bm * 128) / p.Bn;
    const int i0 = (bm * 128) % p.Bn;
    if (i0 >= p.nt[dir * MAXL + t]) return;

    extern __shared__ float smem[];
    float* As = smem;                               // [4][2560]
    float* Bs = smem + G_STAGES * GA_FLOATS;        // [4][5120]

    const float* Bmat = dir ? p.Bw1 : p.Bw0;
    float* C          = dir ? p.C1  : p.C0;

    const int tid = threadIdx.x, warp = tid >> 5, lane = tid & 31;
    const int wm = (warp & 1) * 64;
    const int wn = (warp >> 1) * 64;
    const int lr = tid >> 2, lc = (tid & 3) * 4;

    const float* arow[2];
    #pragma unroll
    for (int q = 0; q < 2; ++q) {
        const int i   = i0 + lr + q * 64;
        const int b   = p.perm[i];
        const int len = dir ? p.lenb_s[i] : p.lenf_s[i];
        int idx = dir ? (6 + len - t) : (8 - len + t);
        idx = min(max(idx, 0), T_WIN - 1);
        arow[q] = p.win + ((size_t)b * T_WIN + idx) * D_DIM;
    }
    const float* brow[4];
    #pragma unroll
    for (int q = 0; q < 4; ++q)
        brow[q] = Bmat + (size_t)(bn * 256 + lr + q * 64) * D_DIM;

    float acc[4][8][4];
    #pragma unroll
    for (int i = 0; i < 4; ++i)
        #pragma unroll
        for (int tt = 0; tt < 8; ++tt)
            #pragma unroll
            for (int v = 0; v < 4; ++v) acc[i][tt][v] = 0.f;

    const int KT = D_DIM >> 4;   // 32

#define G_LOAD(S, KI)                                                          \
    do {                                                                       \
        if ((KI) < KT) {                                                       \
            const int K0 = (KI) * 16;                                          \
            float* dA = As + (S) * GA_FLOATS + lr * PITCH + lc;                \
            cpasync16(dA,              arow[0] + K0 + lc);                     \
            cpasync16(dA + 64 * PITCH, arow[1] + K0 + lc);                     \
            float* dB = Bs + (S) * GB_FLOATS + lr * PITCH + lc;                \
            cpasync16(dB,               brow[0] + K0 + lc);                    \
            cpasync16(dB +  64 * PITCH, brow[1] + K0 + lc);                    \
            cpasync16(dB + 128 * PITCH, brow[2] + K0 + lc);                    \
            cpasync16(dB + 192 * PITCH, brow[3] + K0 + lc);                    \
        }                                                                      \
        CP_COMMIT();                                                           \
    } while (0)

    #pragma unroll
    for (int s = 0; s < G_STAGES - 1; ++s) G_LOAD(s, s);

    for (int kt = 0; kt < KT; ++kt) {
        CP_WAIT(G_STAGES - 2);
        __syncthreads();

        const int buf = kt & (G_STAGES - 1);
        const float* Ab = As + buf * GA_FLOATS;
        const float* Bb = Bs + buf * GB_FLOATS;

        #pragma unroll
        for (int ks = 0; ks < 2; ++ks) {
            const int k0 = ks * 8;
            unsigned a[4][4];
            #pragma unroll
            for (int i = 0; i < 4; ++i)
                ldsm4(a[i], Ab + (wm + i * 16 + (lane & 15)) * PITCH
                               + k0 + (lane >> 4) * 4);
            unsigned b[4][4];
            #pragma unroll
            for (int t4 = 0; t4 < 4; ++t4)
                ldsm4(b[t4], Bb + (wn + t4 * 16 + ((lane >> 4) << 3)
                                   + (lane & 7)) * PITCH
                                + k0 + ((lane >> 3) & 1) * 4);
            #pragma unroll
            for (int i = 0; i < 4; ++i)
                #pragma unroll
                for (int t4 = 0; t4 < 4; ++t4) {
                    mma_tf32(acc[i][2 * t4],     a[i], b[t4][0], b[t4][1]);
                    mma_tf32(acc[i][2 * t4 + 1], a[i], b[t4][2], b[t4][3]);
                }
        }

        G_LOAD((kt + G_STAGES - 1) & (G_STAGES - 1), kt + G_STAGES - 1);
    }
#undef G_LOAD

    const int qr = lane >> 2;
    const int qc = (lane & 3) * 2;
    #pragma unroll
    for (int i = 0; i < 4; ++i) {
        const int r0 = bm * 128 + wm + i * 16 + qr;   // global M index (t*Bn+i)
        #pragma unroll
        for (int tt = 0; tt < 8; ++tt) {
            const int cc = bn * 256 + wn + tt * 8 + qc;
            *(float2*)(C + (size_t)r0      * G3 + cc) =
                make_float2(acc[i][tt][0], acc[i][tt][1]);
            *(float2*)(C + (size_t)(r0 + 8) * G3 + cc) =
                make_float2(acc[i][tt][2], acc[i][tt][3]);
        }
    }
}

// ---------------------------------------------------------------------------
// Fused recurrence step: gh = h_in @ Whh^T (3 gate blocks) + gate -> h_out.
// Block: 128 rows x 128 gate-cols, 3 accumulator sets (r,z,n). 3-stage pipe.
// h double-buffered across steps (no intra-step write/read race).
// ---------------------------------------------------------------------------
struct FuseP {
    const float* hin0;  const float* hin1;
    float*       hout0; float*       hout1;
    const float* Whh0;  const float* Whh1;   // prerounded (1536,512)
    const float* xp0;   const float* xp1;
    const float* bih0;  const float* bih1;
    const float* bhh0;  const float* bhh1;
    const int*   nt;
    int t, Bn;
};

__global__ __launch_bounds__(256, 1)
void gemm_fused_gate(FuseP p)
{
    const int dir = blockIdx.z, bm = blockIdx.y, bn = blockIdx.x;
    const int t    = p.t;
    const int nact = p.nt[dir * MAXL + t];
    if (bm * 128 >= nact) return;

    extern __shared__ float smem[];   // stage s: [A | Br | Bz | Bn] x 2560

    const float* hin  = dir ? p.hin1  : p.hin0;
    float*       hout = dir ? p.hout1 : p.hout0;
    const float* W    = dir ? p.Whh1  : p.Whh0;
    const float* xp   = dir ? p.xp1   : p.xp0;
    const float* bih  = dir ? p.bih1  : p.bih0;
    const float* bhh  = dir ? p.bhh1  : p.bhh0;

    const int tid = threadIdx.x, warp = tid >> 5, lane = tid & 31;
    const int wm = (warp >> 1) * 32;
    const int wn = (warp & 1) * 64;
    const int lr = tid >> 2, lc = (tid & 3) * 4;

    const float* arow0 = hin + (size_t)(bm * 128 + lr) * H_DIM;
    const float* arow1 = arow0 + (size_t)64 * H_DIM;
    const float* brow[3][2];
    #pragma unroll
    for (int g = 0; g < 3; ++g) {
        brow[g][0] = W + (size_t)(g * 512 + bn * 128 + lr) * H_DIM;
        brow[g][1] = brow[g][0] + (size_t)64 * H_DIM;
    }

    float acc[3][2][8][4];
    #pragma unroll
    for (int g = 0; g < 3; ++g)
        #pragma unroll
        for (int i = 0; i < 2; ++i)
            #pragma unroll
            for (int tt = 0; tt < 8; ++tt)
                #pragma unroll
                for (int v = 0; v < 4; ++v) acc[g][i][tt][v] = 0.f;

    const int KT = H_DIM >> 4;   // 32

#define F_LOAD(S, KI)                                                          \
    do {                                                                       \
        if ((KI) < KT) {                                                       \
            const int K0 = (KI) * 16;                                          \
            float* base = smem + (S) * 4 * F_TILE_FLOATS;                      \
            float* dA = base + lr * PITCH + lc;                                \
            cpasync16(dA,              arow0 + K0 + lc);                       \
            cpasync16(dA + 64 * PITCH, arow1 + K0 + lc);                       \
            _Pragma("unroll")                                                  \
            for (int g_ = 0; g_ < 3; ++g_) {                                   \
                float* dB = base + (g_ + 1) * F_TILE_FLOATS + lr * PITCH + lc; \
                cpasync16(dB,              brow[g_][0] + K0 + lc);             \
                cpasync16(dB + 64 * PITCH, brow[g_][1] + K0 + lc);             \
            }                                                                  \
        }                                                                      \
        CP_COMMIT();                                                           \
    } while (0)

    F_LOAD(0, 0);
    F_LOAD(1, 1);

    for (int kt = 0; kt < KT; ++kt) {
        CP_WAIT(1);
        __syncthreads();

        const int buf = kt % F_STAGES;
        const float* base = smem + buf * 4 * F_TILE_FLOATS;

        #pragma unroll
        for (int ks = 0; ks < 2; ++ks) {
            const int k0 = ks * 8;
            unsigned a[2][4];
            #pragma unroll
            for (int i = 0; i < 2; ++i)
                ldsm4(a[i], base + (wm + i * 16 + (lane & 15)) * PITCH
                                 + k0 + (lane >> 4) * 4);
            #pragma unroll
            for (int g = 0; g < 3; ++g) {
                const float* Bb = base + (g + 1) * F_TILE_FLOATS;
                unsigned b[4][4];
                #pragma unroll
                for (int t4 = 0; t4 < 4; ++t4)
                    ldsm4(b[t4], Bb + (wn + t4 * 16 + ((lane >> 4) << 3)
                                       + (lane & 7)) * PITCH
                                    + k0 + ((lane >> 3) & 1) * 4);
                #pragma unroll
                for (int i = 0; i < 2; ++i)
                    #pragma unroll
                    for (int t4 = 0; t4 < 4; ++t4) {
                        mma_tf32(acc[g][i][2 * t4],     a[i], b[t4][0], b[t4][1]);
                        mma_tf32(acc[g][i][2 * t4 + 1], a[i], b[t4][2], b[t4][3]);
                    }
            }
        }

        F_LOAD((kt + 2) % F_STAGES, kt + 2);
    }
#undef F_LOAD

    // ---- fused gate epilogue ----
    const int qr = lane >> 2;
    const int qc = (lane & 3) * 2;
    #pragma unroll
    for (int i = 0; i < 2; ++i) {
        const int rbase = bm * 128 + wm + i * 16 + qr;
        #pragma unroll
        for (int tt = 0; tt < 8; ++tt) {
            const int cc = bn * 128 + wn + tt * 8 + qc;   // gate col in [0,512)
            const float2 br2 = *(const float2*)(bih + cc);
            const float2 bz2 = *(const float2*)(bih + 512 + cc);
            const float2 bq2 = *(const float2*)(bih + 1024 + cc);
            const float2 cr2 = *(const float2*)(bhh + cc);
            const float2 cz2 = *(const float2*)(bhh + 512 + cc);
            const float2 cq2 = *(const float2*)(bhh + 1024 + cc);
            #pragma unroll
            for (int half = 0; half < 2; ++half) {
                const int r = rbase + half * 8;
                if (r >= nact) continue;
                const float gr0 = acc[0][i][tt][half * 2];
                const float gr1 = acc[0][i][tt][half * 2 + 1];
                const float gz0 = acc[1][i][tt][half * 2];
                const float gz1 = acc[1][i][tt][half * 2 + 1];
                const float gn0 = acc[2][i][tt][half * 2];
                const float gn1 = acc[2][i][tt][half * 2 + 1];
                const float* xq = xp + ((size_t)t * p.Bn + r) * G3 + cc;
                const float2 xr2 = *(const float2*)(xq);
                const float2 xz2 = *(const float2*)(xq + 512);
                const float2 xn2 = *(const float2*)(xq + 1024);
                const float2 hp2 = *(const float2*)(hin + (size_t)r * H_DIM + cc);

                float rr0 = 1.f / (1.f + expf(-(xr2.x + br2.x + gr0 + cr2.x)));
                float rr1 = 1.f / (1.f + expf(-(xr2.y + br2.y + gr1 + cr2.y)));
                float zz0 = 1.f / (1.f + expf(-(xz2.x + bz2.x + gz0 + cz2.x)));
                float zz1 = 1.f / (1.f + expf(-(xz2.y + bz2.y + gz1 + cz2.y)));
                float nn0 = tanhf(xn2.x + bq2.x + rr0 * (gn0 + cq2.x));
                float nn1 = tanhf(xn2.y + bq2.y + rr1 * (gn1 + cq2.y));
                float h0 = (1.f - zz0) * nn0 + zz0 * hp2.x;
                float h1 = (1.f - zz1) * nn1 + zz1 * hp2.y;
                h0 = __uint_as_float(f2tf32(h0));
                h1 = __uint_as_float(f2tf32(h1));
                *(float2*)(hout + (size_t)r * H_DIM + cc) = make_float2(h0, h1);
            }
        }
    }
}

// ---------------------------------------------------------------------------
// MLP GEMM (CONCAT with per-row h-buffer select, and final PLAIN+scatter)
// ---------------------------------------------------------------------------
enum { MODE_PLAIN = 1, MODE_CONCAT = 2 };
enum { EPI_BIAS = 1, EPI_BIAS_RELU = 2 };

struct GemmP {
    const float* A0;   // PLAIN: A base | CONCAT: h_f buffer A
    const float* A0b;  // CONCAT: h_f buffer B
    const float* A1;   // CONCAT: h_b buffer A
    const float* A1b;  // CONCAT: h_b buffer B
    const float* B0;
    float*       C0;
    const float* bias;
    const int*   lenf_s;
    const int*   lenb_s;
    const int*   operm;
    int M, N, K;
};

template<int MODE, int EPI, int RND>
__global__ __launch_bounds__(256, 2)
void gemm_tc(GemmP p)
{
    extern __shared__ char dsm[];
    float* As = (float*)dsm;
    float* Bs = (float*)(dsm + STAGES * STAGE_FLOATS * 4);

    const float* __restrict__ Bmat = p.B0;
    float* __restrict__ C          = p.C0;
    const int K = p.K;
    const int N = p.N;

    const int tid  = threadIdx.x;
    const int bm   = blockIdx.y;
    const int bn   = blockIdx.x;
    const int warp = tid >> 5;
    const int lane = tid & 31;
    const int wm   = (warp >> 1) * 32;
    const int wn   = (warp & 1) * 64;

    const int lr = tid >> 2;
    const int lc = (tid & 3) * 4;

    const float *af0 = nullptr, *af1 = nullptr, *ab0 = nullptr, *ab1 = nullptr;
    if (MODE == MODE_CONCAT) {
        #pragma unroll
        for (int q = 0; q < 2; ++q) {
            const int r  = bm * 128 + lr + q * 64;
            const int lf = p.lenf_s[r];
            const int lb = p.lenb_s[r];
            const float* fb = ((lf - 1) & 1) ? p.A0b : p.A0;
            const float* bb = ((lb - 1) & 1) ? p.A1b : p.A1;
            if (q == 0) { af0 = fb + (size_t)r * 512; ab0 = bb + (size_t)r * 512; }
            else        { af1 = fb + (size_t)r * 512; ab1 = bb + (size_t)r * 512; }
        }
    } else {
        af0 = p.A0 + (size_t)(bm * 128 + lr) * K;
        af1 = af0 + (size_t)64 * K;
    }

    const float* brow0 = Bmat + (size_t)(bn * 128 + lr) * K;
    const float* brow1 = brow0 + (size_t)64 * K;

    float acc[2][8][4];
    #pragma unroll
    for (int i = 0; i < 2; ++i)
        #pragma unroll
        for (int t = 0; t < 8; ++t)
            #pragma unroll
            for (int v = 0; v < 4; ++v) acc[i][t][v] = 0.f;

    const int KT = K >> 4;

#define LOAD_STAGE(S, KT_IDX)                                                  \
    do {                                                                       \
        if ((KT_IDX) < KT) {                                                   \
            const int K0 = (KT_IDX) * 16;                                      \
            float* da0 = As + (S) * STAGE_FLOATS + lr * PITCH + lc;            \
            float* db0 = Bs + (S) * STAGE_FLOATS + lr * PITCH + lc;            \
            const float *pa0, *pa1;                                            \
            if (MODE == MODE_CONCAT) {                                         \
                pa0 = ((K0 < 512) ? af0 : ab0) + (K0 & 511) + lc;              \
                pa1 = ((K0 < 512) ? af1 : ab1) + (K0 & 511) + lc;              \
            } else {                                                           \
                pa0 = af0 + K0 + lc;                                           \
                pa1 = af1 + K0 + lc;                                           \
            }                                                                  \
            cpasync16(da0,              pa0);                                  \
            cpasync16(da0 + 64 * PITCH, pa1);                                  \
            cpasync16(db0,              brow0 + K0 + lc);                      \
            cpasync16(db0 + 64 * PITCH, brow1 + K0 + lc);                      \
        }                                                                      \
        CP_COMMIT();                                                           \
    } while (0)

    #pragma unroll
    for (int s = 0; s < STAGES - 1; ++s) LOAD_STAGE(s, s);

    for (int kt = 0; kt < KT; ++kt) {
        CP_WAIT(STAGES - 2);
        __syncthreads();

        const int buf = kt & (STAGES - 1);
        const float* Ab = As + buf * STAGE_FLOATS;
        const float* Bb = Bs + buf * STAGE_FLOATS;

        #pragma unroll
        for (int ks = 0; ks < 2; ++ks) {
            const int k0 = ks * 8;
            unsigned a[2][4];
            #pragma unroll
            for (int i = 0; i < 2; ++i)
                ldsm4(a[i], Ab + (wm + i * 16 + (lane & 15)) * PITCH
                               + k0 + (lane >> 4) * 4);
            unsigned b[4][4];
            #pragma unroll
            for (int t4 = 0; t4 < 4; ++t4)
                ldsm4(b[t4], Bb + (wn + t4 * 16 + ((lane >> 4) << 3)
                                   + (lane & 7)) * PITCH
                                + k0 + ((lane >> 3) & 1) * 4);
            #pragma unroll
            for (int i = 0; i < 2; ++i)
                #pragma unroll
                for (int t4 = 0; t4 < 4; ++t4) {
                    mma_tf32(acc[i][2 * t4],     a[i], b[t4][0], b[t4][1]);
                    mma_tf32(acc[i][2 * t4 + 1], a[i], b[t4][2], b[t4][3]);
                }
        }

        LOAD_STAGE((kt + STAGES - 1) & (STAGES - 1), kt + STAGES - 1);
    }
#undef LOAD_STAGE

    const int qr = lane >> 2;
    const int qc = (lane & 3) * 2;
    #pragma unroll
    for (int i = 0; i < 2; ++i) {
        const int rA = bm * 128 + wm + i * 16 + qr;
        const int gA = p.operm ? p.operm[rA]     : rA;
        const int gB = p.operm ? p.operm[rA + 8] : rA + 8;
        #pragma unroll
        for (int t = 0; t < 8; ++t) {
            const int cc = bn * 128 + wn + t * 8 + qc;
            float v0 = acc[i][t][0], v1 = acc[i][t][1];
            float v2 = acc[i][t][2], v3 = acc[i][t][3];
            float b0 = p.bias[cc], b1 = p.bias[cc + 1];
            v0 += b0; v1 += b1; v2 += b0; v3 += b1;
            if (EPI == EPI_BIAS_RELU) {
                v0 = fmaxf(v0, 0.f); v1 = fmaxf(v1, 0.f);
                v2 = fmaxf(v2, 0.f); v3 = fmaxf(v3, 0.f);
            }
            if (RND) {
                v0 = __uint_as_float(f2tf32(v0));
                v1 = __uint_as_float(f2tf32(v1));
                v2 = __uint_as_float(f2tf32(v2));
                v3 = __uint_as_float(f2tf32(v3));
            }
            *(float2*)(C + (size_t)gA * N + cc) = make_float2(v0, v1);
            *(float2*)(C + (size_t)gB * N + cc) = make_float2(v2, v3);
        }
    }
}

// ---------------------------------------------------------------------------
// GRU gate, t=0 only (h_prev = 0, gh = 0): h = (1-z)*n, all rows active.
// ---------------------------------------------------------------------------
struct GateP {
    const float* xp0; const float* xp1;
    float*       h0;  float*       h1;
    const float* bih0; const float* bih1;
    const float* bhh0; const float* bhh1;
    int Bn;
};

__global__ void gru_gate0(GateP p)
{
    const int dir = blockIdx.z;
    const int gi  = blockIdx.x * blockDim.x + threadIdx.x;
    const int i   = gi >> 7;
    const int j   = (gi & 127) * 4;

    const float* xp = (dir ? p.xp1 : p.xp0) + (size_t)i * G3 + j;  // t=0 block
    float4 xr = *(const float4*)(xp);
    float4 xz = *(const float4*)(xp + 512);
    float4 xn = *(const float4*)(xp + 1024);

    const float* bih = (dir ? p.bih1 : p.bih0) + j;
    const float* bhh = (dir ? p.bhh1 : p.bhh0) + j;
    float4 br = *(const float4*)(bih);
    float4 bz = *(const float4*)(bih + 512);
    float4 bq = *(const float4*)(bih + 1024);
    float4 cr = *(const float4*)(bhh);
    float4 cz = *(const float4*)(bhh + 512);
    float4 cq = *(const float4*)(bhh + 1024);

    float* hp = (dir ? p.h1 : p.h0) + (size_t)i * H_DIM + j;

    float4 res;
#define GATE(c)                                                                \
    {                                                                          \
        float r = 1.f / (1.f + expf(-(xr.c + br.c + cr.c)));                   \
        float z = 1.f / (1.f + expf(-(xz.c + bz.c + cz.c)));                   \
        float n = tanhf(xn.c + bq.c + r * cq.c);                               \
        float h = (1.f - z) * n;                                               \
        res.c = __uint_as_float(f2tf32(h));                                    \
    }
    GATE(x) GATE(y) GATE(z) GATE(w)
#undef GATE
    *(float4*)hp = res;
}

// ---------------------------------------------------------------------------
// Launch sequence (graph-capturable)
// ---------------------------------------------------------------------------
extern "C" void kernel_launch(void* const* d_in, const int* in_sizes, int n_in,
                              void* d_out, int out_size)
{
    const float* win   = (const float*)d_in[0];
    const int*   wlen  = (const int*)  d_in[1];
    const float* Wih_f = (const float*)d_in[2];
    const float* Whh_f = (const float*)d_in[3];
    const float* bih_f = (const float*)d_in[4];
    const float* bhh_f = (const float*)d_in[5];
    const float* Wih_b = (const float*)d_in[6];
    const float* Whh_b = (const float*)d_in[7];
    const float* bih_b = (const float*)d_in[8];
    const float* bhh_b = (const float*)d_in[9];
    const float* W1    = (const float*)d_in[10];
    const float* b1    = (const float*)d_in[11];
    const float* W2    = (const float*)d_in[12];
    const float* b2    = (const float*)d_in[13];
    float* out = (float*)d_out;

    const int Bn = in_sizes[1];

    float *xp0, *xp1, *h0a, *h0b, *h1a, *h1b, *hid, *winr, *wr;
    int *perm, *lenf_s, *lenb_s, *nt;
    cudaGetSymbolAddress((void**)&xp0,    g_xp0);
    cudaGetSymbolAddress((void**)&xp1,    g_xp1);
    cudaGetSymbolAddress((void**)&h0a,    g_h0a);
    cudaGetSymbolAddress((void**)&h0b,    g_h0b);
    cudaGetSymbolAddress((void**)&h1a,    g_h1a);
    cudaGetSymbolAddress((void**)&h1b,    g_h1b);
    cudaGetSymbolAddress((void**)&hid,    g_hid);
    cudaGetSymbolAddress((void**)&winr,   g_winr);
    cudaGetSymbolAddress((void**)&wr,     g_wr);
    cudaGetSymbolAddress((void**)&perm,   g_perm);
    cudaGetSymbolAddress((void**)&lenf_s, g_lenf_s);
    cudaGetSymbolAddress((void**)&lenb_s, g_lenb_s);
    cudaGetSymbolAddress((void**)&nt,     g_nt);

    static bool attr_done = false;
    if (!attr_done) {
        cudaFuncSetAttribute(gemm_gather256,
                             cudaFuncAttributeMaxDynamicSharedMemorySize, GSMEM_REQ);
        cudaFuncSetAttribute(gemm_fused_gate,
                             cudaFuncAttributeMaxDynamicSharedMemorySize, FSMEM_REQ);
        cudaFuncSetAttribute(gemm_tc<MODE_CONCAT, EPI_BIAS_RELU, 1>,
                             cudaFuncAttributeMaxDynamicSharedMemorySize, SMEM_REQ);
        cudaFuncSetAttribute(gemm_tc<MODE_PLAIN, EPI_BIAS, 0>,
                             cudaFuncAttributeMaxDynamicSharedMemorySize, SMEM_REQ);
        attr_done = true;
    }

    // --- 0a) Pre-round GEMM inputs to canonical tf32 ---
    {
        int n4 = Bn * T_WIN * D_DIM / 4;
        preround<<<(n4 + 255) / 256, 256>>>((const float4*)win,
                                            (float4*)winr, n4);
        int w4 = G3 * D_DIM / 4;
        preround<<<(w4 + 255) / 256, 256>>>((const float4*)Wih_f,
                                            (float4*)(wr + WR_WIHF), w4);
        preround<<<(w4 + 255) / 256, 256>>>((const float4*)Whh_f,
                                            (float4*)(wr + WR_WHHF), w4);
        preround<<<(w4 + 255) / 256, 256>>>((const float4*)Wih_b,
                                            (float4*)(wr + WR_WIHB), w4);
        preround<<<(w4 + 255) / 256, 256>>>((const float4*)Whh_b,
                                            (float4*)(wr + WR_WHHB), w4);
        int m4 = H_DIM * 2 * H_DIM / 4;
        preround<<<(m4 + 255) / 256, 256>>>((const float4*)W1,
                                            (float4*)(wr + WR_W1), m4);
        int o4 = H_DIM * H_DIM / 4;
        preround<<<(o4 + 255) / 256, 256>>>((const float4*)W2,
                                            (float4*)(wr + WR_W2), o4);
    }

    // --- 0b) Deterministic counting sort by wl descending ---
    const int nchunks = Bn / 256;
    sort1<<<nchunks, 256>>>(wlen);
    sort2<<<1, 32>>>(nchunks);
    sort3<<<nchunks, 256>>>(wlen);

    // --- 1) Input projections (gathered, 128x256 tiles, compaction) ---
    GathP pg = {};
    pg.win = winr;
    pg.Bw0 = wr + WR_WIHF; pg.Bw1 = wr + WR_WIHB;
    pg.C0 = xp0; pg.C1 = xp1;
    pg.perm = perm; pg.lenf_s = lenf_s; pg.lenb_s = lenb_s; pg.nt = nt;
    pg.Bn = Bn;
    gemm_gather256<<<dim3(G3 / 256, Bn * MAXL / 128, 2), 256, GSMEM_REQ>>>(pg);

    // --- 2) t=0 gate (h=0 case), then fused GEMM+gate steps t=1..7 ---
    GateP gp;
    gp.xp0 = xp0; gp.xp1 = xp1;
    gp.h0 = h0a;  gp.h1 = h1a;
    gp.bih0 = bih_f; gp.bih1 = bih_b;
    gp.bhh0 = bhh_f; gp.bhh1 = bhh_b;
    gp.Bn = Bn;
    gru_gate0<<<dim3((Bn * (H_DIM / 4)) / 256, 1, 2), 256>>>(gp);

    FuseP fp = {};
    fp.Whh0 = wr + WR_WHHF; fp.Whh1 = wr + WR_WHHB;
    fp.xp0 = xp0; fp.xp1 = xp1;
    fp.bih0 = bih_f; fp.bih1 = bih_b;
    fp.bhh0 = bhh_f; fp.bhh1 = bhh_b;
    fp.nt = nt; fp.Bn = Bn;
    for (int t = 1; t < MAXL; ++t) {
        const bool in_a = ((t - 1) & 1) == 0;     // step t reads buf[(t-1)&1]
        fp.hin0  = in_a ? h0a : h0b;
        fp.hin1  = in_a ? h1a : h1b;
        fp.hout0 = in_a ? h0b : h0a;
        fp.hout1 = in_a ? h1b : h1a;
        fp.t = t;
        gemm_fused_gate<<<dim3(H_DIM / 128, Bn / 128, 2), 256, FSMEM_REQ>>>(fp);
    }

    // --- 3) MLP: relu([h_f,h_b] @ W1^T + b1) @ W2^T + b2 (+scatter) ---
    GemmP p3 = {};
    p3.A0 = h0a; p3.A0b = h0b;
    p3.A1 = h1a; p3.A1b = h1b;
    p3.B0 = wr + WR_W1;
    p3.C0 = hid;
    p3.bias = b1;
    p3.lenf_s = lenf_s; p3.lenb_s = lenb_s;
    p3.M = Bn; p3.N = H_DIM; p3.K = 2 * H_DIM;
    gemm_tc<MODE_CONCAT, EPI_BIAS_RELU, 1>
        <<<dim3(H_DIM / 128, Bn / 128, 1), 256, SMEM_REQ>>>(p3);

    GemmP p4 = {};
    p4.A0 = hid;
    p4.B0 = wr + WR_W2;
    p4.C0 = out;
    p4.bias = b2;
    p4.operm = perm;
    p4.M = Bn; p4.N = H_DIM; p4.K = H_DIM;
    gemm_tc<MODE_PLAIN, EPI_BIAS, 0>
        <<<dim3(H_DIM / 128, Bn / 128, 1), 256, SMEM_REQ>>>(p4);
}

// round 7
// speedup vs baseline: 1.8279x; 1.8279x over previous
#include <cuda_runtime.h>
#include <cuda_fp16.h>
#include <math.h>
#include <cstdint>

// ---------------------------------------------------------------------------
// Problem constants: B=8192, T=15, D=H=512, MAXL=8, CENTER=7
// ---------------------------------------------------------------------------
#define B_MAX   8192
#define T_WIN   15
#define D_DIM   512
#define H_DIM   512
#define G3      1536
#define MAXL    8

#define PITCH_H      40                    // smem row pitch in halfs (80 B)
#define STAGES       4                     // K32 stages
#define STAGE_HALFS  (128 * PITCH_H)       // 5120 halfs = 10240 B
#define SMEM_REQ     (STAGES * STAGE_HALFS * 2 * 2)   // 81920 B

// ---------------------------------------------------------------------------
// Scratch
// ---------------------------------------------------------------------------
__device__ float  g_xp0[B_MAX * MAXL * G3];   // [t][sorted_i][1536] fwd (fp32)
__device__ float  g_xp1[B_MAX * MAXL * G3];
__device__ float  g_gh0[B_MAX * G3];          // h@Whh^T (fp32)
__device__ float  g_gh1[B_MAX * G3];
__device__ __half g_h0 [B_MAX * H_DIM];       // hidden states (fp16, sorted)
__device__ __half g_h1 [B_MAX * H_DIM];
__device__ __half g_hid[B_MAX * H_DIM];       // MLP hidden (fp16)
__device__ __half g_winh[B_MAX * T_WIN * D_DIM];  // fp16 window
#define WH_WIHF 0
#define WH_WHHF (G3 * D_DIM)
#define WH_WIHB (2 * G3 * D_DIM)
#define WH_WHHB (3 * G3 * D_DIM)
#define WH_W1   (4 * G3 * D_DIM)
#define WH_W2   (4 * G3 * D_DIM + H_DIM * 2 * H_DIM)
__device__ __half g_wh[4 * G3 * D_DIM + H_DIM * 2 * H_DIM + H_DIM * H_DIM];

// ---- length-compaction state ----
#define MAX_CHUNKS 64
__device__ int g_chunk_hist[MAX_CHUNKS][16];
__device__ int g_chunk_base[MAX_CHUNKS][16];
__device__ int g_lrank [B_MAX];
__device__ int g_perm  [B_MAX];
__device__ int g_lenf_s[B_MAX];
__device__ int g_lenb_s[B_MAX];
__device__ int g_nt[2 * MAXL];

// ---------------------------------------------------------------------------
// PTX helpers
// ---------------------------------------------------------------------------
__device__ __forceinline__ void ldsm4(unsigned* r, const __half* p) {
    unsigned addr = (unsigned)__cvta_generic_to_shared(p);
    asm volatile("ldmatrix.sync.aligned.m8n8.x4.shared.b16 {%0,%1,%2,%3}, [%4];"
                 : "=r"(r[0]), "=r"(r[1]), "=r"(r[2]), "=r"(r[3]) : "r"(addr));
}

__device__ __forceinline__ void mma_f16(float* c, const unsigned* a,
                                        unsigned b0, unsigned b1) {
    asm volatile(
        "mma.sync.aligned.m16n8k16.row.col.f32.f16.f16.f32 "
        "{%0,%1,%2,%3}, {%4,%5,%6,%7}, {%8,%9}, {%0,%1,%2,%3};"
        : "+f"(c[0]), "+f"(c[1]), "+f"(c[2]), "+f"(c[3])
        : "r"(a[0]), "r"(a[1]), "r"(a[2]), "r"(a[3]), "r"(b0), "r"(b1));
}

__device__ __forceinline__ void cpasync16(void* sp, const void* gp) {
    unsigned sa = (unsigned)__cvta_generic_to_shared(sp);
    asm volatile("cp.async.cg.shared.global [%0], [%1], 16;"
                 :: "r"(sa), "l"(gp) : "memory");
}
#define CP_COMMIT() asm volatile("cp.async.commit_group;" ::: "memory")
#define CP_WAIT(N)  asm volatile("cp.async.wait_group %0;" :: "n"(N) : "memory")

// ---------------------------------------------------------------------------
// fp32 -> fp16 conversion (8 elems per thread)
// ---------------------------------------------------------------------------
__global__ void tohalf(const float4* __restrict__ src,
                       uint4* __restrict__ dst, int n8) {
    int i = blockIdx.x * blockDim.x + threadIdx.x;
    if (i >= n8) return;
    float4 a = src[2 * i], b = src[2 * i + 1];
    __half2 h0 = __floats2half2_rn(a.x, a.y);
    __half2 h1 = __floats2half2_rn(a.z, a.w);
    __half2 h2 = __floats2half2_rn(b.x, b.y);
    __half2 h3 = __floats2half2_rn(b.z, b.w);
    uint4 o;
    o.x = *(unsigned*)&h0; o.y = *(unsigned*)&h1;
    o.z = *(unsigned*)&h2; o.w = *(unsigned*)&h3;
    dst[i] = o;
}

// ---------------------------------------------------------------------------
// Deterministic counting sort by window_len descending
// ---------------------------------------------------------------------------
__global__ void sort1(const int* __restrict__ wlen) {
    __shared__ int s_wl[256];
    __shared__ int s_rank[256];
    __shared__ int s_h[16];
    const int c = blockIdx.x, tid = threadIdx.x;
    s_wl[tid] = wlen[c * 256 + tid];
    if (tid < 16) s_h[tid] = 0;
    __syncthreads();
    if (tid == 0) {
        #pragma unroll 4
        for (int k = 0; k < 256; ++k) { int w = s_wl[k]; s_rank[k] = s_h[w]++; }
    }
    __syncthreads();
    g_lrank[c * 256 + tid] = s_rank[tid];
    if (tid < 16) g_chunk_hist[c][tid] = s_h[tid];
}

__global__ void sort2(int nchunks) {
    if (threadIdx.x != 0) return;
    int total[16];
    for (int w = 0; w < 16; ++w) {
        int s = 0;
        for (int c = 0; c < nchunks; ++c) s += g_chunk_hist[c][w];
        total[w] = s;
    }
    int off = 0;
    for (int w = 15; w >= 1; --w) {
        int run = off;
        for (int c = 0; c < nchunks; ++c) {
            g_chunk_base[c][w] = run;
            run += g_chunk_hist[c][w];
        }
        off += total[w];
    }
    for (int t = 0; t < MAXL; ++t) {
        int nf = 0, nb = 0;
        for (int w = 1; w <= 15; ++w) {
            if ((w - 1) / 2 + 1 > t) nf += total[w];
            if (w / 2 + 1 > t)       nb += total[w];
        }
        g_nt[t]        = nf;
        g_nt[MAXL + t] = nb;
    }
}

__global__ void sort3(const int* __restrict__ wlen) {
    const int c = blockIdx.x;
    const int i = c * 256 + threadIdx.x;
    const int w = wlen[i];
    const int pos = g_chunk_base[c][w] + g_lrank[i];
    g_perm[pos]   = i;
    g_lenf_s[pos] = (w - 1) / 2 + 1;
    g_lenb_s[pos] = w / 2 + 1;
}

// ---------------------------------------------------------------------------
// fp16 tensor-core NT GEMM: C[M,N] = A[M,K] @ B[N,K]^T  (fp32 accum)
// 128x128 block, K32 stages, 4-deep cp.async, 256 thr, 2 CTAs/SM.
// OUTH=1 -> C is __half (MLP hidden); else fp32 (+optional row scatter).
// ---------------------------------------------------------------------------
enum { MODE_GATHER = 0, MODE_PLAIN = 1, MODE_CONCAT = 2 };
enum { EPI_NONE = 0, EPI_BIAS = 1, EPI_BIAS_RELU = 2 };

struct GemmP {
    const __half* A0;     // PLAIN: A | CONCAT: h_f
    const __half* A1;     // CONCAT: h_b
    const __half* B0;     // dir-0 weights (N,K) fp16
    const __half* B1;
    void*         C0;     // dir-0 output
    void*         C1;
    const __half* win;
    const float*  bias;
    const int*    perm;
    const int*    lenf_s;
    const int*    lenb_s;
    const int*    nt;
    const int*    operm;
    int M, N, K, step, Bn;
};

template<int MODE, int EPI, int OUTH>
__global__ __launch_bounds__(256, 2)
void gemm_f16(GemmP p)
{
    const int dir = blockIdx.z;
    const int bm  = blockIdx.y;
    const int bn  = blockIdx.x;

    // ---- length-compaction early exit ----
    if (MODE == MODE_GATHER) {
        const int t  = (bm * 128) / p.Bn;
        const int i0 = (bm * 128) % p.Bn;
        if (i0 >= p.nt[dir * MAXL + t]) return;
    } else if (p.nt) {
        if (bm * 128 >= p.nt[dir * MAXL + p.step]) return;
    }

    extern __shared__ __half hsm[];
    __half* As = hsm;
    __half* Bs = hsm + STAGES * STAGE_HALFS;

    const __half* __restrict__ Bmat = dir ? p.B1 : p.B0;
    const int K = p.K;
    const int N = p.N;

    const int tid  = threadIdx.x;
    const int warp = tid >> 5;
    const int lane = tid & 31;
    const int wm   = (warp >> 1) * 32;
    const int wn   = (warp & 1) * 64;

    // global-load mapping: rows lr, lr+64; chunk lc = 8 halfs (16 B)
    const int lr = tid >> 2;
    const int lc = (tid & 3) * 8;

    const __half* arow0 = nullptr;
    const __half* arow1 = nullptr;
    const __half* ab0 = nullptr;   // CONCAT second half (h_b rows)
    const __half* ab1 = nullptr;

    if (MODE == MODE_GATHER) {
        #pragma unroll
        for (int q = 0; q < 2; ++q) {
            const int gr = bm * 128 + lr + q * 64;
            const int t  = gr / p.Bn;
            const int i  = gr % p.Bn;
            const int b  = p.perm[i];
            const int len = dir ? p.lenb_s[i] : p.lenf_s[i];
            int idx = dir ? (6 + len - t) : (8 - len + t);
            idx = min(max(idx, 0), T_WIN - 1);
            const __half* rp = p.win + ((size_t)b * T_WIN + idx) * D_DIM;
            if (q == 0) arow0 = rp; else arow1 = rp;
        }
    } else if (MODE == MODE_PLAIN) {
        arow0 = (dir ? p.A1 : p.A0) + (size_t)(bm * 128 + lr) * K;
        arow1 = arow0 + (size_t)64 * K;
    } else {   // CONCAT: rows from h_f (K 0..511) and h_b (K 512..1023)
        const int r0 = bm * 128 + lr;
        arow0 = p.A0 + (size_t)r0 * 512;
        arow1 = p.A0 + (size_t)(r0 + 64) * 512;
        ab0   = p.A1 + (size_t)r0 * 512;
        ab1   = p.A1 + (size_t)(r0 + 64) * 512;
    }

    const __half* brow0 = Bmat + (size_t)(bn * 128 + lr) * K;
    const __half* brow1 = brow0 + (size_t)64 * K;

    float acc[2][8][4];
    #pragma unroll
    for (int i = 0; i < 2; ++i)
        #pragma unroll
        for (int t = 0; t < 8; ++t)
            #pragma unroll
            for (int v = 0; v < 4; ++v) acc[i][t][v] = 0.f;

    const int KT = K >> 5;   // K32 stages

#define LOAD_STAGE(S, KI)                                                      \
    do {                                                                       \
        if ((KI) < KT) {                                                       \
            const int K0 = (KI) * 32;                                          \
            __half* da = As + (S) * STAGE_HALFS + lr * PITCH_H + lc;           \
            __half* db = Bs + (S) * STAGE_HALFS + lr * PITCH_H + lc;           \
            const __half *pa0, *pa1;                                           \
            if (MODE == MODE_CONCAT) {                                         \
                pa0 = ((K0 < 512) ? arow0 : ab0) + (K0 & 511) + lc;            \
                pa1 = ((K0 < 512) ? arow1 : ab1) + (K0 & 511) + lc;            \
            } else {                                                           \
                pa0 = arow0 + K0 + lc;                                         \
                pa1 = arow1 + K0 + lc;                                         \
            }                                                                  \
            cpasync16(da,                pa0);                                 \
            cpasync16(da + 64 * PITCH_H, pa1);                                 \
            cpasync16(db,                brow0 + K0 + lc);                     \
            cpasync16(db + 64 * PITCH_H, brow1 + K0 + lc);                     \
        }                                                                      \
        CP_COMMIT();                                                           \
    } while (0)

    #pragma unroll
    for (int s = 0; s < STAGES - 1; ++s) LOAD_STAGE(s, s);

    for (int kt = 0; kt < KT; ++kt) {
        CP_WAIT(STAGES - 2);
        __syncthreads();

        const int buf = kt & (STAGES - 1);
        const __half* Ab = As + buf * STAGE_HALFS;
        const __half* Bb = Bs + buf * STAGE_HALFS;

        #pragma unroll
        for (int ks = 0; ks < 2; ++ks) {      // two k16 sub-steps per K32
            const int k0 = ks * 16;
            unsigned a[2][4];
            #pragma unroll
            for (int i = 0; i < 2; ++i)
                ldsm4(a[i], Ab + (wm + i * 16 + (lane & 15)) * PITCH_H
                               + k0 + (lane >> 4) * 8);
            unsigned b[4][4];
            #pragma unroll
            for (int t4 = 0; t4 < 4; ++t4)
                ldsm4(b[t4], Bb + (wn + t4 * 16 + ((lane >> 4) << 3)
                                   + (lane & 7)) * PITCH_H
                                + k0 + ((lane >> 3) & 1) * 8);
            #pragma unroll
            for (int i = 0; i < 2; ++i)
                #pragma unroll
                for (int t4 = 0; t4 < 4; ++t4) {
                    mma_f16(acc[i][2 * t4],     a[i], b[t4][0], b[t4][1]);
                    mma_f16(acc[i][2 * t4 + 1], a[i], b[t4][2], b[t4][3]);
                }
        }

        LOAD_STAGE((kt + STAGES - 1) & (STAGES - 1), kt + STAGES - 1);
    }
#undef LOAD_STAGE

    // ---- epilogue ----
    const int qr = lane >> 2;
    const int qc = (lane & 3) * 2;
    #pragma unroll
    for (int i = 0; i < 2; ++i) {
        const int rA = bm * 128 + wm + i * 16 + qr;
        const int gA = p.operm ? p.operm[rA]     : rA;
        const int gB = p.operm ? p.operm[rA + 8] : rA + 8;
        #pragma unroll
        for (int t = 0; t < 8; ++t) {
            const int cc = bn * 128 + wn + t * 8 + qc;
            float v0 = acc[i][t][0], v1 = acc[i][t][1];
            float v2 = acc[i][t][2], v3 = acc[i][t][3];
            if (EPI != EPI_NONE) {
                float b0 = p.bias[cc], b1 = p.bias[cc + 1];
                v0 += b0; v1 += b1; v2 += b0; v3 += b1;
                if (EPI == EPI_BIAS_RELU) {
                    v0 = fmaxf(v0, 0.f); v1 = fmaxf(v1, 0.f);
                    v2 = fmaxf(v2, 0.f); v3 = fmaxf(v3, 0.f);
                }
            }
            if (OUTH) {
                __half* Ch = (__half*)(dir ? p.C1 : p.C0);
                *(__half2*)(Ch + (size_t)gA * N + cc) = __floats2half2_rn(v0, v1);
                *(__half2*)(Ch + (size_t)gB * N + cc) = __floats2half2_rn(v2, v3);
            } else {
                float* Cf = (float*)(dir ? p.C1 : p.C0);
                *(float2*)(Cf + (size_t)gA * N + cc) = make_float2(v0, v1);
                *(float2*)(Cf + (size_t)gB * N + cc) = make_float2(v2, v3);
            }
        }
    }
}

// ---------------------------------------------------------------------------
// GRU gate update on sorted rows (prefix-active). h stored fp16.
// ---------------------------------------------------------------------------
struct GateP {
    const float* xp0; const float* xp1;
    const float* gh0; const float* gh1;
    __half*      h0;  __half*      h1;
    const float* bih0; const float* bih1;
    const float* bhh0; const float* bhh1;
    const int*   nt;
    int t, Bn;
};

__global__ void gru_gate(GateP p)
{
    const int dir = blockIdx.z;
    const int gi  = blockIdx.x * blockDim.x + threadIdx.x;
    const int i   = gi >> 7;
    const int j   = (gi & 127) * 4;
    const int t   = p.t;

    if (i >= p.nt[dir * MAXL + t]) return;

    const float* xp = (dir ? p.xp1 : p.xp0)
                    + ((size_t)t * p.Bn + i) * G3 + j;
    float4 xr = *(const float4*)(xp);
    float4 xz = *(const float4*)(xp + 512);
    float4 xn = *(const float4*)(xp + 1024);

    const float* bih = (dir ? p.bih1 : p.bih0) + j;
    const float* bhh = (dir ? p.bhh1 : p.bhh0) + j;
    float4 br = *(const float4*)(bih);
    float4 bz = *(const float4*)(bih + 512);
    float4 bq = *(const float4*)(bih + 1024);
    float4 cr = *(const float4*)(bhh);
    float4 cz = *(const float4*)(bhh + 512);
    float4 cq = *(const float4*)(bhh + 1024);

    __half* hp = (dir ? p.h1 : p.h0) + (size_t)i * H_DIM + j;
    float4 hr, hz, hq, hv;
    if (t > 0) {
        const float* gh = (dir ? p.gh1 : p.gh0) + (size_t)i * G3 + j;
        hr = *(const float4*)(gh);
        hz = *(const float4*)(gh + 512);
        hq = *(const float4*)(gh + 1024);
        __half2 hv01 = *(const __half2*)(hp);
        __half2 hv23 = *(const __half2*)(hp + 2);
        float2 f01 = __half22float2(hv01);
        float2 f23 = __half22float2(hv23);
        hv = make_float4(f01.x, f01.y, f23.x, f23.y);
    } else {
        hr = hz = hq = make_float4(0.f, 0.f, 0.f, 0.f);
        hv = make_float4(0.f, 0.f, 0.f, 0.f);
    }

    float4 res;
#define GATE(c)                                                                \
    {                                                                          \
        float r = 1.f / (1.f + expf(-(xr.c + br.c + hr.c + cr.c)));            \
        float z = 1.f / (1.f + expf(-(xz.c + bz.c + hz.c + cz.c)));            \
        float n = tanhf(xn.c + bq.c + r * (hq.c + cq.c));                      \
        res.c = (1.f - z) * n + z * hv.c;                                      \
    }
    GATE(x) GATE(y) GATE(z) GATE(w)
#undef GATE
    *(__half2*)(hp)     = __floats2half2_rn(res.x, res.y);
    *(__half2*)(hp + 2) = __floats2half2_rn(res.z, res.w);
}

// ---------------------------------------------------------------------------
// Launch sequence (graph-capturable)
// ---------------------------------------------------------------------------
extern "C" void kernel_launch(void* const* d_in, const int* in_sizes, int n_in,
                              void* d_out, int out_size)
{
    const float* win   = (const float*)d_in[0];
    const int*   wlen  = (const int*)  d_in[1];
    const float* Wih_f = (const float*)d_in[2];
    const float* Whh_f = (const float*)d_in[3];
    const float* bih_f = (const float*)d_in[4];
    const float* bhh_f = (const float*)d_in[5];
    const float* Wih_b = (const float*)d_in[6];
    const float* Whh_b = (const float*)d_in[7];
    const float* bih_b = (const float*)d_in[8];
    const float* bhh_b = (const float*)d_in[9];
    const float* W1    = (const float*)d_in[10];
    const float* b1    = (const float*)d_in[11];
    const float* W2    = (const float*)d_in[12];
    const float* b2    = (const float*)d_in[13];
    float* out = (float*)d_out;

    const int Bn = in_sizes[1];

    float *xp0, *xp1, *gh0, *gh1;
    __half *h0, *h1, *hid, *winh, *wh;
    int *perm, *lenf_s, *lenb_s, *nt;
    cudaGetSymbolAddress((void**)&xp0,    g_xp0);
    cudaGetSymbolAddress((void**)&xp1,    g_xp1);
    cudaGetSymbolAddress((void**)&gh0,    g_gh0);
    cudaGetSymbolAddress((void**)&gh1,    g_gh1);
    cudaGetSymbolAddress((void**)&h0,     g_h0);
    cudaGetSymbolAddress((void**)&h1,     g_h1);
    cudaGetSymbolAddress((void**)&hid,    g_hid);
    cudaGetSymbolAddress((void**)&winh,   g_winh);
    cudaGetSymbolAddress((void**)&wh,     g_wh);
    cudaGetSymbolAddress((void**)&perm,   g_perm);
    cudaGetSymbolAddress((void**)&lenf_s, g_lenf_s);
    cudaGetSymbolAddress((void**)&lenb_s, g_lenb_s);
    cudaGetSymbolAddress((void**)&nt,     g_nt);

    static bool attr_done = false;
    if (!attr_done) {
        cudaFuncSetAttribute(gemm_f16<MODE_GATHER, EPI_NONE, 0>,
                             cudaFuncAttributeMaxDynamicSharedMemorySize, SMEM_REQ);
        cudaFuncSetAttribute(gemm_f16<MODE_PLAIN, EPI_NONE, 0>,
                             cudaFuncAttributeMaxDynamicSharedMemorySize, SMEM_REQ);
        cudaFuncSetAttribute(gemm_f16<MODE_CONCAT, EPI_BIAS_RELU, 1>,
                             cudaFuncAttributeMaxDynamicSharedMemorySize, SMEM_REQ);
        cudaFuncSetAttribute(gemm_f16<MODE_PLAIN, EPI_BIAS, 0>,
                             cudaFuncAttributeMaxDynamicSharedMemorySize, SMEM_REQ);
        attr_done = true;
    }

    // --- 0a) Convert GEMM inputs to fp16 ---
    {
        int n8 = Bn * T_WIN * D_DIM / 8;
        tohalf<<<(n8 + 255) / 256, 256>>>((const float4*)win, (uint4*)winh, n8);
        int w8 = G3 * D_DIM / 8;
        tohalf<<<(w8 + 255) / 256, 256>>>((const float4*)Wih_f,
                                          (uint4*)(wh + WH_WIHF), w8);
        tohalf<<<(w8 + 255) / 256, 256>>>((const float4*)Whh_f,
                                          (uint4*)(wh + WH_WHHF), w8);
        tohalf<<<(w8 + 255) / 256, 256>>>((const float4*)Wih_b,
                                          (uint4*)(wh + WH_WIHB), w8);
        tohalf<<<(w8 + 255) / 256, 256>>>((const float4*)Whh_b,
                                          (uint4*)(wh + WH_WHHB), w8);
        int m8 = H_DIM * 2 * H_DIM / 8;
        tohalf<<<(m8 + 255) / 256, 256>>>((const float4*)W1,
                                          (uint4*)(wh + WH_W1), m8);
        int o8 = H_DIM * H_DIM / 8;
        tohalf<<<(o8 + 255) / 256, 256>>>((const float4*)W2,
                                          (uint4*)(wh + WH_W2), o8);
    }

    // --- 0b) Deterministic counting sort by wl descending ---
    const int nchunks = Bn / 256;
    sort1<<<nchunks, 256>>>(wlen);
    sort2<<<1, 32>>>(nchunks);
    sort3<<<nchunks, 256>>>(wlen);

    // --- 1) Input projections (gathered, t-major sorted, compaction) ---
    GemmP p1 = {};
    p1.win = winh;
    p1.B0 = wh + WH_WIHF; p1.B1 = wh + WH_WIHB;
    p1.C0 = xp0;          p1.C1 = xp1;
    p1.perm = perm; p1.lenf_s = lenf_s; p1.lenb_s = lenb_s; p1.nt = nt;
    p1.M = Bn * MAXL; p1.N = G3; p1.K = D_DIM; p1.Bn = Bn;
    gemm_f16<MODE_GATHER, EPI_NONE, 0>
        <<<dim3(G3 / 128, p1.M / 128, 2), 256, SMEM_REQ>>>(p1);

    // --- 2) Recurrence over sorted prefix ---
    GateP gp;
    gp.xp0 = xp0; gp.xp1 = xp1;
    gp.gh0 = gh0; gp.gh1 = gh1;
    gp.h0  = h0;  gp.h1  = h1;
    gp.bih0 = bih_f; gp.bih1 = bih_b;
    gp.bhh0 = bhh_f; gp.bhh1 = bhh_b;
    gp.nt = nt; gp.Bn = Bn;

    const dim3 ggrid((Bn * (H_DIM / 4)) / 256, 1, 2);
    gp.t = 0;
    gru_gate<<<ggrid, 256>>>(gp);

    GemmP p2 = {};
    p2.A0 = h0; p2.A1 = h1;
    p2.B0 = wh + WH_WHHF; p2.B1 = wh + WH_WHHB;
    p2.C0 = gh0;          p2.C1 = gh1;
    p2.nt = nt;
    p2.M = Bn; p2.N = G3; p2.K = H_DIM; p2.Bn = Bn;
    for (int t = 1; t < MAXL; ++t) {
        p2.step = t;
        gemm_f16<MODE_PLAIN, EPI_NONE, 0>
            <<<dim3(G3 / 128, Bn / 128, 2), 256, SMEM_REQ>>>(p2);
        gp.t = t;
        gru_gate<<<ggrid, 256>>>(gp);
    }

    // --- 3) MLP: relu([h_f,h_b] @ W1^T + b1) @ W2^T + b2 (+scatter) ---
    GemmP p3 = {};
    p3.A0 = h0; p3.A1 = h1;
    p3.B0 = wh + WH_W1; p3.B1 = wh + WH_W1;
    p3.C0 = hid; p3.C1 = hid;
    p3.bias = b1;
    p3.M = Bn; p3.N = H_DIM; p3.K = 2 * H_DIM; p3.Bn = Bn;
    gemm_f16<MODE_CONCAT, EPI_BIAS_RELU, 1>
        <<<dim3(H_DIM / 128, Bn / 128, 1), 256, SMEM_REQ>>>(p3);

    GemmP p4 = {};
    p4.A0 = hid; p4.A1 = hid;
    p4.B0 = wh + WH_W2; p4.B1 = wh + WH_W2;
    p4.C0 = out; p4.C1 = out;
    p4.bias = b2;
    p4.operm = perm;
    p4.M = Bn; p4.N = H_DIM; p4.K = H_DIM; p4.Bn = Bn;
    gemm_f16<MODE_PLAIN, EPI_BIAS, 0>
        <<<dim3(H_DIM / 128, Bn / 128, 1), 256, SMEM_REQ>>>(p4);
}

// round 8
// speedup vs baseline: 1.8941x; 1.0362x over previous
#include <cuda_runtime.h>
#include <cuda_fp16.h>
#include <math.h>
#include <cstdint>

// ---------------------------------------------------------------------------
// Problem constants: B=8192, T=15, D=H=512, MAXL=8, CENTER=7
// ---------------------------------------------------------------------------
#define B_MAX   8192
#define T_WIN   15
#define D_DIM   512
#define H_DIM   512
#define G3      1536
#define MAXL    8

#define PITCH_H      40                    // smem row pitch in halfs (80 B)
#define STAGES       4                     // K32 stages
#define STAGE_HALFS  (128 * PITCH_H)       // 5120 halfs = 10240 B
#define SMEM_REQ     (STAGES * STAGE_HALFS * 2 * 2)   // 81920 B

// ---------------------------------------------------------------------------
// Scratch (all GEMM-facing intermediates in fp16)
// ---------------------------------------------------------------------------
__device__ __half g_xp0[B_MAX * MAXL * G3];   // [t][sorted_i][1536] fwd
__device__ __half g_xp1[B_MAX * MAXL * G3];
__device__ __half g_gh0[B_MAX * G3];          // h@Whh^T
__device__ __half g_gh1[B_MAX * G3];
__device__ __half g_h0 [B_MAX * H_DIM];       // hidden states (sorted)
__device__ __half g_h1 [B_MAX * H_DIM];
__device__ __half g_hid[B_MAX * H_DIM];       // MLP hidden
__device__ __half g_winh[B_MAX * T_WIN * D_DIM];  // fp16 window
#define WH_WIHF 0
#define WH_WHHF (G3 * D_DIM)
#define WH_WIHB (2 * G3 * D_DIM)
#define WH_WHHB (3 * G3 * D_DIM)
#define WH_W1   (4 * G3 * D_DIM)
#define WH_W2   (4 * G3 * D_DIM + H_DIM * 2 * H_DIM)
__device__ __half g_wh[4 * G3 * D_DIM + H_DIM * 2 * H_DIM + H_DIM * H_DIM];

// ---- length-compaction state ----
#define MAX_CHUNKS 64
__device__ int g_chunk_hist[MAX_CHUNKS][16];
__device__ int g_chunk_base[MAX_CHUNKS][16];
__device__ int g_lrank [B_MAX];
__device__ int g_perm  [B_MAX];
__device__ int g_lenf_s[B_MAX];
__device__ int g_lenb_s[B_MAX];
__device__ int g_nt[2 * MAXL];

// ---------------------------------------------------------------------------
// PTX helpers
// ---------------------------------------------------------------------------
__device__ __forceinline__ void ldsm4(unsigned* r, const __half* p) {
    unsigned addr = (unsigned)__cvta_generic_to_shared(p);
    asm volatile("ldmatrix.sync.aligned.m8n8.x4.shared.b16 {%0,%1,%2,%3}, [%4];"
                 : "=r"(r[0]), "=r"(r[1]), "=r"(r[2]), "=r"(r[3]) : "r"(addr));
}

__device__ __forceinline__ void mma_f16(float* c, const unsigned* a,
                                        unsigned b0, unsigned b1) {
    asm volatile(
        "mma.sync.aligned.m16n8k16.row.col.f32.f16.f16.f32 "
        "{%0,%1,%2,%3}, {%4,%5,%6,%7}, {%8,%9}, {%0,%1,%2,%3};"
        : "+f"(c[0]), "+f"(c[1]), "+f"(c[2]), "+f"(c[3])
        : "r"(a[0]), "r"(a[1]), "r"(a[2]), "r"(a[3]), "r"(b0), "r"(b1));
}

__device__ __forceinline__ void cpasync16(void* sp, const void* gp) {
    unsigned sa = (unsigned)__cvta_generic_to_shared(sp);
    asm volatile("cp.async.cg.shared.global [%0], [%1], 16;"
                 :: "r"(sa), "l"(gp) : "memory");
}
#define CP_COMMIT() asm volatile("cp.async.commit_group;" ::: "memory")
#define CP_WAIT(N)  asm volatile("cp.async.wait_group %0;" :: "n"(N) : "memory")

// load 4 consecutive halfs -> float4
__device__ __forceinline__ float4 ldh4(const __half* p) {
    __half2 a = *(const __half2*)(p);
    __half2 b = *(const __half2*)(p + 2);
    float2 fa = __half22float2(a);
    float2 fb = __half22float2(b);
    return make_float4(fa.x, fa.y, fb.x, fb.y);
}

// ---------------------------------------------------------------------------
// fp32 -> fp16 conversion (8 elems per thread)
// ---------------------------------------------------------------------------
__global__ void tohalf(const float4* __restrict__ src,
                       uint4* __restrict__ dst, int n8) {
    int i = blockIdx.x * blockDim.x + threadIdx.x;
    if (i >= n8) return;
    float4 a = src[2 * i], b = src[2 * i + 1];
    __half2 h0 = __floats2half2_rn(a.x, a.y);
    __half2 h1 = __floats2half2_rn(a.z, a.w);
    __half2 h2 = __floats2half2_rn(b.x, b.y);
    __half2 h3 = __floats2half2_rn(b.z, b.w);
    uint4 o;
    o.x = *(unsigned*)&h0; o.y = *(unsigned*)&h1;
    o.z = *(unsigned*)&h2; o.w = *(unsigned*)&h3;
    dst[i] = o;
}

// ---------------------------------------------------------------------------
// Deterministic counting sort by window_len descending
// ---------------------------------------------------------------------------
__global__ void sort1(const int* __restrict__ wlen) {
    __shared__ int s_wl[256];
    __shared__ int s_rank[256];
    __shared__ int s_h[16];
    const int c = blockIdx.x, tid = threadIdx.x;
    s_wl[tid] = wlen[c * 256 + tid];
    if (tid < 16) s_h[tid] = 0;
    __syncthreads();
    if (tid == 0) {
        #pragma unroll 4
        for (int k = 0; k < 256; ++k) { int w = s_wl[k]; s_rank[k] = s_h[w]++; }
    }
    __syncthreads();
    g_lrank[c * 256 + tid] = s_rank[tid];
    if (tid < 16) g_chunk_hist[c][tid] = s_h[tid];
}

__global__ void sort2(int nchunks) {
    if (threadIdx.x != 0) return;
    int total[16];
    for (int w = 0; w < 16; ++w) {
        int s = 0;
        for (int c = 0; c < nchunks; ++c) s += g_chunk_hist[c][w];
        total[w] = s;
    }
    int off = 0;
    for (int w = 15; w >= 1; --w) {
        int run = off;
        for (int c = 0; c < nchunks; ++c) {
            g_chunk_base[c][w] = run;
            run += g_chunk_hist[c][w];
        }
        off += total[w];
    }
    for (int t = 0; t < MAXL; ++t) {
        int nf = 0, nb = 0;
        for (int w = 1; w <= 15; ++w) {
            if ((w - 1) / 2 + 1 > t) nf += total[w];
            if (w / 2 + 1 > t)       nb += total[w];
        }
        g_nt[t]        = nf;
        g_nt[MAXL + t] = nb;
    }
}

__global__ void sort3(const int* __restrict__ wlen) {
    const int c = blockIdx.x;
    const int i = c * 256 + threadIdx.x;
    const int w = wlen[i];
    const int pos = g_chunk_base[c][w] + g_lrank[i];
    g_perm[pos]   = i;
    g_lenf_s[pos] = (w - 1) / 2 + 1;
    g_lenb_s[pos] = w / 2 + 1;
}

// ---------------------------------------------------------------------------
// fp16 tensor-core NT GEMM: C[M,N] = A[M,K] @ B[N,K]^T  (fp32 accum)
// 128x128 block, K32 stages, 4-deep cp.async, 256 thr, 2 CTAs/SM.
// OUTH=1 -> C is __half; else fp32 (+optional row scatter).
// ---------------------------------------------------------------------------
enum { MODE_GATHER = 0, MODE_PLAIN = 1, MODE_CONCAT = 2 };
enum { EPI_NONE = 0, EPI_BIAS = 1, EPI_BIAS_RELU = 2 };

struct GemmP {
    const __half* A0;     // PLAIN: A | CONCAT: h_f
    const __half* A1;     // CONCAT: h_b
    const __half* B0;     // dir-0 weights (N,K) fp16
    const __half* B1;
    void*         C0;     // dir-0 output
    void*         C1;
    const __half* win;
    const float*  bias;
    const int*    perm;
    const int*    lenf_s;
    const int*    lenb_s;
    const int*    nt;
    const int*    operm;
    int M, N, K, step, Bn;
};

template<int MODE, int EPI, int OUTH>
__global__ __launch_bounds__(256, 2)
void gemm_f16(GemmP p)
{
    const int dir = blockIdx.z;
    const int bm  = blockIdx.y;
    const int bn  = blockIdx.x;

    // ---- length-compaction early exit ----
    if (MODE == MODE_GATHER) {
        const int t  = (bm * 128) / p.Bn;
        const int i0 = (bm * 128) % p.Bn;
        if (i0 >= p.nt[dir * MAXL + t]) return;
    } else if (p.nt) {
        if (bm * 128 >= p.nt[dir * MAXL + p.step]) return;
    }

    extern __shared__ __half hsm[];
    __half* As = hsm;
    __half* Bs = hsm + STAGES * STAGE_HALFS;

    const __half* __restrict__ Bmat = dir ? p.B1 : p.B0;
    const int K = p.K;
    const int N = p.N;

    const int tid  = threadIdx.x;
    const int warp = tid >> 5;
    const int lane = tid & 31;
    const int wm   = (warp >> 1) * 32;
    const int wn   = (warp & 1) * 64;

    const int lr = tid >> 2;
    const int lc = (tid & 3) * 8;

    const __half* arow0 = nullptr;
    const __half* arow1 = nullptr;
    const __half* ab0 = nullptr;
    const __half* ab1 = nullptr;

    if (MODE == MODE_GATHER) {
        #pragma unroll
        for (int q = 0; q < 2; ++q) {
            const int gr = bm * 128 + lr + q * 64;
            const int t  = gr / p.Bn;
            const int i  = gr % p.Bn;
            const int b  = p.perm[i];
            const int len = dir ? p.lenb_s[i] : p.lenf_s[i];
            int idx = dir ? (6 + len - t) : (8 - len + t);
            idx = min(max(idx, 0), T_WIN - 1);
            const __half* rp = p.win + ((size_t)b * T_WIN + idx) * D_DIM;
            if (q == 0) arow0 = rp; else arow1 = rp;
        }
    } else if (MODE == MODE_PLAIN) {
        arow0 = (dir ? p.A1 : p.A0) + (size_t)(bm * 128 + lr) * K;
        arow1 = arow0 + (size_t)64 * K;
    } else {
        const int r0 = bm * 128 + lr;
        arow0 = p.A0 + (size_t)r0 * 512;
        arow1 = p.A0 + (size_t)(r0 + 64) * 512;
        ab0   = p.A1 + (size_t)r0 * 512;
        ab1   = p.A1 + (size_t)(r0 + 64) * 512;
    }

    const __half* brow0 = Bmat + (size_t)(bn * 128 + lr) * K;
    const __half* brow1 = brow0 + (size_t)64 * K;

    float acc[2][8][4];
    #pragma unroll
    for (int i = 0; i < 2; ++i)
        #pragma unroll
        for (int t = 0; t < 8; ++t)
            #pragma unroll
            for (int v = 0; v < 4; ++v) acc[i][t][v] = 0.f;

    const int KT = K >> 5;

#define LOAD_STAGE(S, KI)                                                      \
    do {                                                                       \
        if ((KI) < KT) {                                                       \
            const int K0 = (KI) * 32;                                          \
            __half* da = As + (S) * STAGE_HALFS + lr * PITCH_H + lc;           \
            __half* db = Bs + (S) * STAGE_HALFS + lr * PITCH_H + lc;           \
            const __half *pa0, *pa1;                                           \
            if (MODE == MODE_CONCAT) {                                         \
                pa0 = ((K0 < 512) ? arow0 : ab0) + (K0 & 511) + lc;            \
                pa1 = ((K0 < 512) ? arow1 : ab1) + (K0 & 511) + lc;            \
            } else {                                                           \
                pa0 = arow0 + K0 + lc;                                         \
                pa1 = arow1 + K0 + lc;                                         \
            }                                                                  \
            cpasync16(da,                pa0);                                 \
            cpasync16(da + 64 * PITCH_H, pa1);                                 \
            cpasync16(db,                brow0 + K0 + lc);                     \
            cpasync16(db + 64 * PITCH_H, brow1 + K0 + lc);                     \
        }                                                                      \
        CP_COMMIT();                                                           \
    } while (0)

    #pragma unroll
    for (int s = 0; s < STAGES - 1; ++s) LOAD_STAGE(s, s);

    for (int kt = 0; kt < KT; ++kt) {
        CP_WAIT(STAGES - 2);
        __syncthreads();

        const int buf = kt & (STAGES - 1);
        const __half* Ab = As + buf * STAGE_HALFS;
        const __half* Bb = Bs + buf * STAGE_HALFS;

        #pragma unroll
        for (int ks = 0; ks < 2; ++ks) {
            const int k0 = ks * 16;
            unsigned a[2][4];
            #pragma unroll
            for (int i = 0; i < 2; ++i)
                ldsm4(a[i], Ab + (wm + i * 16 + (lane & 15)) * PITCH_H
                               + k0 + (lane >> 4) * 8);
            unsigned b[4][4];
            #pragma unroll
            for (int t4 = 0; t4 < 4; ++t4)
                ldsm4(b[t4], Bb + (wn + t4 * 16 + ((lane >> 4) << 3)
                                   + (lane & 7)) * PITCH_H
                                + k0 + ((lane >> 3) & 1) * 8);
            #pragma unroll
            for (int i = 0; i < 2; ++i)
                #pragma unroll
                for (int t4 = 0; t4 < 4; ++t4) {
                    mma_f16(acc[i][2 * t4],     a[i], b[t4][0], b[t4][1]);
                    mma_f16(acc[i][2 * t4 + 1], a[i], b[t4][2], b[t4][3]);
                }
        }

        LOAD_STAGE((kt + STAGES - 1) & (STAGES - 1), kt + STAGES - 1);
    }
#undef LOAD_STAGE

    // ---- epilogue ----
    const int qr = lane >> 2;
    const int qc = (lane & 3) * 2;
    #pragma unroll
    for (int i = 0; i < 2; ++i) {
        const int rA = bm * 128 + wm + i * 16 + qr;
        const int gA = p.operm ? p.operm[rA]     : rA;
        const int gB = p.operm ? p.operm[rA + 8] : rA + 8;
        #pragma unroll
        for (int t = 0; t < 8; ++t) {
            const int cc = bn * 128 + wn + t * 8 + qc;
            float v0 = acc[i][t][0], v1 = acc[i][t][1];
            float v2 = acc[i][t][2], v3 = acc[i][t][3];
            if (EPI != EPI_NONE) {
                float b0 = p.bias[cc], b1 = p.bias[cc + 1];
                v0 += b0; v1 += b1; v2 += b0; v3 += b1;
                if (EPI == EPI_BIAS_RELU) {
                    v0 = fmaxf(v0, 0.f); v1 = fmaxf(v1, 0.f);
                    v2 = fmaxf(v2, 0.f); v3 = fmaxf(v3, 0.f);
                }
            }
            if (OUTH) {
                __half* Ch = (__half*)(dir ? p.C1 : p.C0);
                *(__half2*)(Ch + (size_t)gA * N + cc) = __floats2half2_rn(v0, v1);
                *(__half2*)(Ch + (size_t)gB * N + cc) = __floats2half2_rn(v2, v3);
            } else {
                float* Cf = (float*)(dir ? p.C1 : p.C0);
                *(float2*)(Cf + (size_t)gA * N + cc) = make_float2(v0, v1);
                *(float2*)(Cf + (size_t)gB * N + cc) = make_float2(v2, v3);
            }
        }
    }
}

// ---------------------------------------------------------------------------
// GRU gate update on sorted rows (prefix-active). xp/gh/h all fp16.
// ---------------------------------------------------------------------------
struct GateP {
    const __half* xp0; const __half* xp1;
    const __half* gh0; const __half* gh1;
    __half*       h0;  __half*       h1;
    const float* bih0; const float* bih1;
    const float* bhh0; const float* bhh1;
    const int*   nt;
    int t, Bn;
};

__global__ void gru_gate(GateP p)
{
    const int dir = blockIdx.z;
    const int gi  = blockIdx.x * blockDim.x + threadIdx.x;
    const int i   = gi >> 7;
    const int j   = (gi & 127) * 4;
    const int t   = p.t;

    if (i >= p.nt[dir * MAXL + t]) return;

    const __half* xp = (dir ? p.xp1 : p.xp0)
                     + ((size_t)t * p.Bn + i) * G3 + j;
    float4 xr = ldh4(xp);
    float4 xz = ldh4(xp + 512);
    float4 xn = ldh4(xp + 1024);

    const float* bih = (dir ? p.bih1 : p.bih0) + j;
    const float* bhh = (dir ? p.bhh1 : p.bhh0) + j;
    float4 br = *(const float4*)(bih);
    float4 bz = *(const float4*)(bih + 512);
    float4 bq = *(const float4*)(bih + 1024);
    float4 cr = *(const float4*)(bhh);
    float4 cz = *(const float4*)(bhh + 512);
    float4 cq = *(const float4*)(bhh + 1024);

    __half* hp = (dir ? p.h1 : p.h0) + (size_t)i * H_DIM + j;
    float4 hr, hz, hq, hv;
    if (t > 0) {
        const __half* gh = (dir ? p.gh1 : p.gh0) + (size_t)i * G3 + j;
        hr = ldh4(gh);
        hz = ldh4(gh + 512);
        hq = ldh4(gh + 1024);
        hv = ldh4(hp);
    } else {
        hr = hz = hq = make_float4(0.f, 0.f, 0.f, 0.f);
        hv = make_float4(0.f, 0.f, 0.f, 0.f);
    }

    float4 res;
#define GATE(c)                                                                \
    {                                                                          \
        float r = 1.f / (1.f + expf(-(xr.c + br.c + hr.c + cr.c)));            \
        float z = 1.f / (1.f + expf(-(xz.c + bz.c + hz.c + cz.c)));            \
        float n = tanhf(xn.c + bq.c + r * (hq.c + cq.c));                      \
        res.c = (1.f - z) * n + z * hv.c;                                      \
    }
    GATE(x) GATE(y) GATE(z) GATE(w)
#undef GATE
    *(__half2*)(hp)     = __floats2half2_rn(res.x, res.y);
    *(__half2*)(hp + 2) = __floats2half2_rn(res.z, res.w);
}

// ---------------------------------------------------------------------------
// Launch sequence (graph-capturable)
// ---------------------------------------------------------------------------
extern "C" void kernel_launch(void* const* d_in, const int* in_sizes, int n_in,
                              void* d_out, int out_size)
{
    const float* win   = (const float*)d_in[0];
    const int*   wlen  = (const int*)  d_in[1];
    const float* Wih_f = (const float*)d_in[2];
    const float* Whh_f = (const float*)d_in[3];
    const float* bih_f = (const float*)d_in[4];
    const float* bhh_f = (const float*)d_in[5];
    const float* Wih_b = (const float*)d_in[6];
    const float* Whh_b = (const float*)d_in[7];
    const float* bih_b = (const float*)d_in[8];
    const float* bhh_b = (const float*)d_in[9];
    const float* W1    = (const float*)d_in[10];
    const float* b1    = (const float*)d_in[11];
    const float* W2    = (const float*)d_in[12];
    const float* b2    = (const float*)d_in[13];
    float* out = (float*)d_out;

    const int Bn = in_sizes[1];

    __half *xp0, *xp1, *gh0, *gh1, *h0, *h1, *hid, *winh, *wh;
    int *perm, *lenf_s, *lenb_s, *nt;
    cudaGetSymbolAddress((void**)&xp0,    g_xp0);
    cudaGetSymbolAddress((void**)&xp1,    g_xp1);
    cudaGetSymbolAddress((void**)&gh0,    g_gh0);
    cudaGetSymbolAddress((void**)&gh1,    g_gh1);
    cudaGetSymbolAddress((void**)&h0,     g_h0);
    cudaGetSymbolAddress((void**)&h1,     g_h1);
    cudaGetSymbolAddress((void**)&hid,    g_hid);
    cudaGetSymbolAddress((void**)&winh,   g_winh);
    cudaGetSymbolAddress((void**)&wh,     g_wh);
    cudaGetSymbolAddress((void**)&perm,   g_perm);
    cudaGetSymbolAddress((void**)&lenf_s, g_lenf_s);
    cudaGetSymbolAddress((void**)&lenb_s, g_lenb_s);
    cudaGetSymbolAddress((void**)&nt,     g_nt);

    static bool attr_done = false;
    if (!attr_done) {
        cudaFuncSetAttribute(gemm_f16<MODE_GATHER, EPI_NONE, 1>,
                             cudaFuncAttributeMaxDynamicSharedMemorySize, SMEM_REQ);
        cudaFuncSetAttribute(gemm_f16<MODE_PLAIN, EPI_NONE, 1>,
                             cudaFuncAttributeMaxDynamicSharedMemorySize, SMEM_REQ);
        cudaFuncSetAttribute(gemm_f16<MODE_CONCAT, EPI_BIAS_RELU, 1>,
                             cudaFuncAttributeMaxDynamicSharedMemorySize, SMEM_REQ);
        cudaFuncSetAttribute(gemm_f16<MODE_PLAIN, EPI_BIAS, 0>,
                             cudaFuncAttributeMaxDynamicSharedMemorySize, SMEM_REQ);
        attr_done = true;
    }

    // --- 0a) Convert GEMM inputs to fp16 ---
    {
        int n8 = Bn * T_WIN * D_DIM / 8;
        tohalf<<<(n8 + 255) / 256, 256>>>((const float4*)win, (uint4*)winh, n8);
        int w8 = G3 * D_DIM / 8;
        tohalf<<<(w8 + 255) / 256, 256>>>((const float4*)Wih_f,
                                          (uint4*)(wh + WH_WIHF), w8);
        tohalf<<<(w8 + 255) / 256, 256>>>((const float4*)Whh_f,
                                          (uint4*)(wh + WH_WHHF), w8);
        tohalf<<<(w8 + 255) / 256, 256>>>((const float4*)Wih_b,
                                          (uint4*)(wh + WH_WIHB), w8);
        tohalf<<<(w8 + 255) / 256, 256>>>((const float4*)Whh_b,
                                          (uint4*)(wh + WH_WHHB), w8);
        int m8 = H_DIM * 2 * H_DIM / 8;
        tohalf<<<(m8 + 255) / 256, 256>>>((const float4*)W1,
                                          (uint4*)(wh + WH_W1), m8);
        int o8 = H_DIM * H_DIM / 8;
        tohalf<<<(o8 + 255) / 256, 256>>>((const float4*)W2,
                                          (uint4*)(wh + WH_W2), o8);
    }

    // --- 0b) Deterministic counting sort by wl descending ---
    const int nchunks = Bn / 256;
    sort1<<<nchunks, 256>>>(wlen);
    sort2<<<1, 32>>>(nchunks);
    sort3<<<nchunks, 256>>>(wlen);

    // --- 1) Input projections (gathered, t-major sorted, compaction) ---
    GemmP p1 = {};
    p1.win = winh;
    p1.B0 = wh + WH_WIHF; p1.B1 = wh + WH_WIHB;
    p1.C0 = xp0;          p1.C1 = xp1;
    p1.perm = perm; p1.lenf_s = lenf_s; p1.lenb_s = lenb_s; p1.nt = nt;
    p1.M = Bn * MAXL; p1.N = G3; p1.K = D_DIM; p1.Bn = Bn;
    gemm_f16<MODE_GATHER, EPI_NONE, 1>
        <<<dim3(G3 / 128, p1.M / 128, 2), 256, SMEM_REQ>>>(p1);

    // --- 2) Recurrence over sorted prefix ---
    GateP gp;
    gp.xp0 = xp0; gp.xp1 = xp1;
    gp.gh0 = gh0; gp.gh1 = gh1;
    gp.h0  = h0;  gp.h1  = h1;
    gp.bih0 = bih_f; gp.bih1 = bih_b;
    gp.bhh0 = bhh_f; gp.bhh1 = bhh_b;
    gp.nt = nt; gp.Bn = Bn;

    const dim3 ggrid((Bn * (H_DIM / 4)) / 256, 1, 2);
    gp.t = 0;
    gru_gate<<<ggrid, 256>>>(gp);

    GemmP p2 = {};
    p2.A0 = h0; p2.A1 = h1;
    p2.B0 = wh + WH_WHHF; p2.B1 = wh + WH_WHHB;
    p2.C0 = gh0;          p2.C1 = gh1;
    p2.nt = nt;
    p2.M = Bn; p2.N = G3; p2.K = H_DIM; p2.Bn = Bn;
    for (int t = 1; t < MAXL; ++t) {
        p2.step = t;
        gemm_f16<MODE_PLAIN, EPI_NONE, 1>
            <<<dim3(G3 / 128, Bn / 128, 2), 256, SMEM_REQ>>>(p2);
        gp.t = t;
        gru_gate<<<ggrid, 256>>>(gp);
    }

    // --- 3) MLP: relu([h_f,h_b] @ W1^T + b1) @ W2^T + b2 (+scatter) ---
    GemmP p3 = {};
    p3.A0 = h0; p3.A1 = h1;
    p3.B0 = wh + WH_W1; p3.B1 = wh + WH_W1;
    p3.C0 = hid; p3.C1 = hid;
    p3.bias = b1;
    p3.M = Bn; p3.N = H_DIM; p3.K = 2 * H_DIM; p3.Bn = Bn;
    gemm_f16<MODE_CONCAT, EPI_BIAS_RELU, 1>
        <<<dim3(H_DIM / 128, Bn / 128, 1), 256, SMEM_REQ>>>(p3);

    GemmP p4 = {};
    p4.A0 = hid; p4.A1 = hid;
    p4.B0 = wh + WH_W2; p4.B1 = wh + WH_W2;
    p4.C0 = out; p4.C1 = out;
    p4.bias = b2;
    p4.operm = perm;
    p4.M = Bn; p4.N = H_DIM; p4.K = H_DIM; p4.Bn = Bn;
    gemm_f16<MODE_PLAIN, EPI_BIAS, 0>
        <<<dim3(H_DIM / 128, Bn / 128, 1), 256, SMEM_REQ>>>(p4);
}